// round 3
// baseline (speedup 1.0000x reference)
#include <cuda_runtime.h>
#include <stdint.h>

// MaskPyramids: out[inst, :] = concat over levels of a 28x28 gaussian window
// placed at the instance's (rounded) position within each level grid.
//
// Strategy: (1) vectorized zero-fill of the whole 109MB output (bandwidth
// bound), (2) scatter the <=784 nonzeros per (instance, level) window.
//
// Rounding replicates XLA's div->mul-by-reciprocal rewrite:
//   lh = rint( fl( fl(p * fl(1/200)) * H ) )   (all f32, round-to-nearest-even)
// 0.005f is bit-exactly fl(1/200). __fmul_rn defeats fast-math rewrites.

#define N_INST   512
#define G        28
#define CTRK     13
#define PER_INST 53294   // 40000 + 10000 + 2500 + 625 + 169

__global__ void zero_fill_kernel(float4* __restrict__ out, int n4) {
    int i = blockIdx.x * blockDim.x + threadIdx.x;
    if (i < n4) out[i] = make_float4(0.f, 0.f, 0.f, 0.f);
}

__global__ void scatter_kernel(const int* __restrict__ pos,
                               const float* __restrict__ mask,
                               float* __restrict__ out) {
    // grid: (N_INST, 5)
    const int inst  = blockIdx.x;
    const int level = blockIdx.y;

    const int Hs[5] = {200, 100, 50, 25, 13};
    const int Bs[5] = {0, 40000, 50000, 52500, 53125};
    const int H    = Hs[level];
    const int base = inst * PER_INST + Bs[level];

    const int p0 = pos[2 * inst + 0];
    const int p1 = pos[2 * inst + 1];

    // XLA-faithful: p * (1/200) * H, all f32 RN, then round-half-even.
    const float recip = 0.005f;  // == fl(1/200) bit-exactly
    const float fh = __fmul_rn(__fmul_rn((float)p0, recip), (float)H);
    const float fw = __fmul_rn(__fmul_rn((float)p1, recip), (float)H);
    const int lh = (int)rintf(fh);
    const int lw = (int)rintf(fw);

    // Window element (si, sj) in [0,28)^2 maps to grid cell
    // a = si + lh - 13, b = sj + lw - 13; write mask[si*28+sj] if in-bounds.
    const int a0 = lh - CTRK;
    const int b0 = lw - CTRK;

    for (int t = threadIdx.x; t < G * G; t += blockDim.x) {
        int si = t / G;
        int sj = t - si * G;
        int a = si + a0;
        int b = sj + b0;
        if ((unsigned)a < (unsigned)H && (unsigned)b < (unsigned)H) {
            out[base + a * H + b] = __ldg(&mask[t]);
        }
    }
}

extern "C" void kernel_launch(void* const* d_in, const int* in_sizes, int n_in,
                              void* d_out, int out_size) {
    const int*   pos  = (const int*)d_in[0];      // int32 [512, 2]
    const float* mask = (const float*)d_in[1];    // float32 [28, 28]
    float*       out  = (float*)d_out;            // float32 [512, 53294]

    // out_size = 512 * 53294 = 27,286,528 — divisible by 4.
    int n4 = out_size >> 2;
    int zblocks = (n4 + 255) / 256;
    zero_fill_kernel<<<zblocks, 256>>>((float4*)out, n4);

    dim3 grid(N_INST, 5);
    scatter_kernel<<<grid, 256>>>(pos, mask, out);
}